// round 12
// baseline (speedup 1.0000x reference)
#include <cuda_runtime.h>
#include <cstdint>

// ---------------------------------------------------------------------------
// EfficientFi VQ-VAE forward, B=1024.  Round 12: kD lane-pair codebook split
// (2 tokens/thread, half codebook/thread, 32 warps/SM).  Rest R11 verbatim
// (kD unroll pragma reverted).
// ---------------------------------------------------------------------------

#define NB 1024
typedef unsigned long long ull;

__device__ float         g_p1[NB * 3200];
__device__ unsigned char g_i1[NB * 3200];
__device__ float         g_vq[NB * 3200];
__device__ unsigned char g_i2[NB * 2400];
__device__ int           g_ind[NB * 128];
__device__ float         g_lat[NB * 2400];
__device__ float         g_lp[128];
__device__ float         g_w2t[27648];   // enc2 weights transposed [(ic*9+k)][96]
__device__ float         g_w1t[27648];   // dec1 weights transposed [(ic*9+k)][32]

// ---------------- f32x2 packed helpers (sm_103a) ----------------
static __device__ __forceinline__ ull f2pk(float a, float b) {
    ull r; asm("mov.b64 %0, {%1, %2};" : "=l"(r) : "f"(a), "f"(b)); return r;
}
static __device__ __forceinline__ void f2un(ull v, float& lo, float& hi) {
    asm("mov.b64 {%0, %1}, %2;" : "=f"(lo), "=f"(hi) : "l"(v));
}
static __device__ __forceinline__ ull f2dup(float a) { return f2pk(a, a); }
static __device__ __forceinline__ ull f2mul(ull a, ull b) {
    ull d; asm("mul.rn.f32x2 %0, %1, %2;" : "=l"(d) : "l"(a), "l"(b)); return d;
}
static __device__ __forceinline__ ull f2fma(ull a, ull b, ull c) {
    ull d; asm("fma.rn.f32x2 %0, %1, %2, %3;" : "=l"(d) : "l"(a), "l"(b), "l"(c)); return d;
}
static __device__ __forceinline__ ull f2add(ull a, ull b) {
    ull d; asm("add.rn.f32x2 %0, %1, %2;" : "=l"(d) : "l"(a), "l"(b)); return d;
}
static __device__ __forceinline__ float f2sum(ull v) {
    float lo, hi; f2un(v, lo, hi); return lo + hi;
}
static __device__ __forceinline__ ull f2mid(ull a, ull b) {
    float alo, ahi, blo, bhi; f2un(a, alo, ahi); f2un(b, blo, bhi);
    return f2pk(ahi, blo);
}

// 12-wide padded row: 6 pairs + 5 mids (kB/kF tiles)
struct Row { ull P[6]; ull M[5]; };
static __device__ __forceinline__ void load_row(const float* __restrict__ rp, Row& R) {
    ulonglong2 q0 = *(const ulonglong2*)(rp);
    ulonglong2 q1 = *(const ulonglong2*)(rp + 4);
    ulonglong2 q2 = *(const ulonglong2*)(rp + 8);
    R.P[0] = q0.x; R.P[1] = q0.y; R.P[2] = q1.x; R.P[3] = q1.y; R.P[4] = q2.x; R.P[5] = q2.y;
#pragma unroll
    for (int k = 0; k < 5; ++k) R.M[k] = f2mid(R.P[k], R.P[k + 1]);
}
static __device__ __forceinline__ void apply_row(const Row& R, ull wa, ull wb, ull wc, ull* acc) {
#pragma unroll
    for (int k = 0; k < 5; ++k) {
        acc[k] = f2fma(wa, R.P[k], acc[k]);
        acc[k] = f2fma(wb, R.M[k], acc[k]);
        acc[k] = f2fma(wc, R.P[k + 1], acc[k]);
    }
}

// 24-wide padded row: 11 pairs + 10 mids (kA tile)
struct Row24 { ull P[11]; ull M[10]; };
static __device__ __forceinline__ void load_row24(const float* __restrict__ rp, Row24& R) {
    ulonglong2 q0 = *(const ulonglong2*)(rp);
    ulonglong2 q1 = *(const ulonglong2*)(rp + 4);
    ulonglong2 q2 = *(const ulonglong2*)(rp + 8);
    ulonglong2 q3 = *(const ulonglong2*)(rp + 12);
    ulonglong2 q4 = *(const ulonglong2*)(rp + 16);
    R.P[0] = q0.x; R.P[1] = q0.y; R.P[2] = q1.x; R.P[3] = q1.y; R.P[4] = q2.x;
    R.P[5] = q2.y; R.P[6] = q3.x; R.P[7] = q3.y; R.P[8] = q4.x; R.P[9] = q4.y;
    R.P[10] = *(const ull*)(rp + 20);
#pragma unroll
    for (int k = 0; k < 10; ++k) R.M[k] = f2mid(R.P[k], R.P[k + 1]);
}
static __device__ __forceinline__ void apply_row24(const Row24& R, ull wa, ull wb, ull wc, ull* acc) {
#pragma unroll
    for (int k = 0; k < 10; ++k) {
        acc[k] = f2fma(wa, R.P[k], acc[k]);
        acc[k] = f2fma(wb, R.M[k], acc[k]);
        acc[k] = f2fma(wc, R.P[k + 1], acc[k]);
    }
}

static __device__ __forceinline__ void pool_epi(ull r0, ull r1, float& best, int& bi) {
    float a00, a01, a10, a11;
    f2un(r0, a00, a01); f2un(r1, a10, a11);
    float v00 = fmaxf(a00, 0.f), v01 = fmaxf(a01, 0.f);
    float v10 = fmaxf(a10, 0.f), v11 = fmaxf(a11, 0.f);
    best = v00; bi = 0;
    if (v01 > best) { best = v01; bi = 1; }
    if (v10 > best) { best = v10; bi = 2; }
    if (v11 > best) { best = v11; bi = 3; }
}

// ---------------------------------------------------------------------------
// kT: one-shot weight transposer.  grid=108, block=512.
// ---------------------------------------------------------------------------
__global__ void __launch_bounds__(512) kT(const float* __restrict__ e2w,
                                          const float* __restrict__ d1w) {
    int i = blockIdx.x * 512 + threadIdx.x;
    if (i < 27648) {
        int kidx = i / 96, oc = i % 96;
        g_w2t[i] = e2w[oc * 288 + kidx];
    } else if (i < 55296) {
        int j = i - 27648;
        int kidx = j / 32, oc = j % 32;
        g_w1t[j] = d1w[oc * 864 + kidx];
    }
}

// ---------------------------------------------------------------------------
// kA: conv1 + relu + pool1, row-based f32x2.  grid=1024, block=320.
// ---------------------------------------------------------------------------
__global__ void __launch_bounds__(320) kA(const float* __restrict__ x,
                                          const float* __restrict__ w,
                                          const float* __restrict__ bias) {
    __shared__ float xp[1728];  // 3 x 24 x 24
    __shared__ float ws[864];
    __shared__ float bs[32];
    const int bb = blockIdx.x;
    const int tid = threadIdx.x;

    for (int i = tid; i < 1728; i += 320) xp[i] = 0.f;
    __syncthreads();
    for (int i = tid; i < 1200; i += 320) {
        int c = i / 400, r = i % 400, y = r / 20, xx = r % 20;
        xp[c * 576 + (y + 1) * 24 + (xx + 1)] = x[bb * 1200 + i];
    }
    for (int i = tid; i < 864; i += 320) ws[i] = w[i];
    if (tid < 32) bs[tid] = bias[tid];
    __syncthreads();

    const int oc = tid & 31;
    const int prow = tid >> 5;         // 0..9
    ull acc0[10], acc1[10];
    {
        ull b = f2dup(bs[oc]);
#pragma unroll
        for (int k = 0; k < 10; ++k) { acc0[k] = b; acc1[k] = b; }
    }
#pragma unroll
    for (int c = 0; c < 3; ++c) {
        const float* wp = ws + (oc * 3 + c) * 9;
        ull w0 = f2dup(wp[0]), w1 = f2dup(wp[1]), w2 = f2dup(wp[2]);
        ull w3 = f2dup(wp[3]), w4 = f2dup(wp[4]), w5 = f2dup(wp[5]);
        ull w6 = f2dup(wp[6]), w7 = f2dup(wp[7]), w8 = f2dup(wp[8]);
        const float* cp = xp + c * 576 + (2 * prow) * 24;
        Row24 R;
        load_row24(cp, R);
        apply_row24(R, w0, w1, w2, acc0);
        load_row24(cp + 24, R);
        apply_row24(R, w3, w4, w5, acc0);
        apply_row24(R, w0, w1, w2, acc1);
        load_row24(cp + 48, R);
        apply_row24(R, w6, w7, w8, acc0);
        apply_row24(R, w3, w4, w5, acc1);
        load_row24(cp + 72, R);
        apply_row24(R, w6, w7, w8, acc1);
    }
#pragma unroll
    for (int k = 0; k < 10; ++k) {
        float best; int bi;
        pool_epi(acc0[k], acc1[k], best, bi);
        const int cell = oc * 100 + prow * 10 + k;
        g_p1[bb * 3200 + cell] = best;
        g_i1[bb * 3200 + cell] = (unsigned char)bi;
    }
}

// ---------------------------------------------------------------------------
// kB: conv2+relu+pool2 (row-based) + pre 1x1 (img-pair, float4 w).
// grid=512 (2 images/CTA), block=480.
// ---------------------------------------------------------------------------
#define SMEM_B_FLOATS (2 * 4608 + 27648 + 96 + 2 * 2400 + 12288 + 128)
__global__ void __launch_bounds__(480) kB(const float* __restrict__ b2,
                                          const float* __restrict__ pw,
                                          const float* __restrict__ pb) {
    extern __shared__ float sm[];
    float* p1p = sm;              // 2 x (32 x 12 x 12)
    float* w2t = p1p + 9216;      // 27648
    float* b2s = w2t + 27648;     // 96
    float* zs  = b2s + 96;        // 2 x (96 x 25)
    float* pws = zs + 4800;       // 12288
    float* pbs = pws + 12288;     // 128
    const int bb = blockIdx.x;
    const int tid = threadIdx.x;

    for (int i = tid; i < 9216; i += 480) p1p[i] = 0.f;
    __syncthreads();
    for (int i = tid; i < 6400; i += 480) {
        int img = i / 3200, r0 = i % 3200;
        int c = r0 / 100, r = r0 % 100, y = r / 10, xx = r % 10;
        p1p[img * 4608 + c * 144 + (y + 1) * 12 + (xx + 1)] = g_p1[(2 * bb + img) * 3200 + r0];
    }
    {
        const float4* s4 = (const float4*)g_w2t;
        float4* d4 = (float4*)w2t;
        for (int i = tid; i < 6912; i += 480) d4[i] = s4[i];
    }
    if (tid < 96) b2s[tid] = b2[tid];
    {
        const float4* s4 = (const float4*)pw;
        float4* d4 = (float4*)pws;
        for (int i = tid; i < 3072; i += 480) d4[i] = s4[i];
    }
    if (tid < 128) pbs[tid] = pb[tid];
    __syncthreads();

    const int item_oc = tid % 96;
    const int prow = tid / 96;            // 0..4
#pragma unroll
    for (int img = 0; img < 2; ++img) {
        const float* tile = p1p + img * 4608 + (2 * prow) * 12;
        float* zsi = zs + img * 2400;
        ull acc0[5], acc1[5];
        {
            ull b = f2dup(b2s[item_oc]);
#pragma unroll
            for (int k = 0; k < 5; ++k) { acc0[k] = b; acc1[k] = b; }
        }
        for (int ic = 0; ic < 32; ++ic) {
            const float* wq = w2t + ic * 9 * 96 + item_oc;
            ull w0 = f2dup(wq[0]),     w1 = f2dup(wq[96]),    w2 = f2dup(wq[192]);
            ull w3 = f2dup(wq[288]),   w4 = f2dup(wq[384]),   w5 = f2dup(wq[480]);
            ull w6 = f2dup(wq[576]),   w7 = f2dup(wq[672]),   w8 = f2dup(wq[768]);
            const float* cp = tile + ic * 144;
            Row R;
            load_row(cp, R);
            apply_row(R, w0, w1, w2, acc0);
            load_row(cp + 12, R);
            apply_row(R, w3, w4, w5, acc0);
            apply_row(R, w0, w1, w2, acc1);
            load_row(cp + 24, R);
            apply_row(R, w6, w7, w8, acc0);
            apply_row(R, w3, w4, w5, acc1);
            load_row(cp + 36, R);
            apply_row(R, w6, w7, w8, acc1);
        }
#pragma unroll
        for (int k = 0; k < 5; ++k) {
            float best; int bi;
            pool_epi(acc0[k], acc1[k], best, bi);
            const int cell = item_oc * 25 + prow * 5 + k;
            zsi[cell] = best;
            g_i2[(2 * bb + img) * 2400 + cell] = (unsigned char)bi;
        }
    }
    __syncthreads();

    // pre 1x1 — per-output chain byte-identical to R6; weights float4, img-pair.
    for (int o = tid; o < 3200; o += 480) {
        const int e = o / 25, s = o % 25;
        const float* wp = pws + e * 96;
        const float* z0 = zs;
        const float* z1 = zs + 2400;
        float a0 = 0.f, a1 = 0.f, a2 = 0.f, a3 = 0.f;
        float b0 = 0.f, b1 = 0.f, b2v = 0.f, b3 = 0.f;
#pragma unroll 4
        for (int c = 0; c < 96; c += 4) {
            const float4 wv = *(const float4*)(wp + c);
            a0 = fmaf(wv.x, z0[(c + 0) * 25 + s], a0);
            a1 = fmaf(wv.y, z0[(c + 1) * 25 + s], a1);
            a2 = fmaf(wv.z, z0[(c + 2) * 25 + s], a2);
            a3 = fmaf(wv.w, z0[(c + 3) * 25 + s], a3);
            b0 = fmaf(wv.x, z1[(c + 0) * 25 + s], b0);
            b1 = fmaf(wv.y, z1[(c + 1) * 25 + s], b1);
            b2v = fmaf(wv.z, z1[(c + 2) * 25 + s], b2v);
            b3 = fmaf(wv.w, z1[(c + 3) * 25 + s], b3);
        }
        g_vq[(2 * bb + 0) * 3200 + o] = (a0 + a1) + (a2 + a3) + pbs[e];
        g_vq[(2 * bb + 1) * 3200 + o] = (b0 + b1) + (b2v + b3) + pbs[e];
    }
}

// ---------------------------------------------------------------------------
// kD: VQ argmin, lane-pair codebook split.  grid=128, block=1024 (32 warps/SM).
// Even lanes scan codes [0,512), odd lanes [512,1024); both hold the same
// 2 tokens; merge via shfl_xor(1).  Per-j scoring chain byte-identical to R10.
// ---------------------------------------------------------------------------
#define SMEM_D_FLOATS (1024 * 28)
__global__ void __launch_bounds__(1024) kD(const float* __restrict__ codebook) {
    extern __shared__ float cb[];
    __shared__ float sred[32];
    const int tid = threadIdx.x;

    {
        const int j = tid;   // 1024 threads <-> 1024 rows
        float nrm = 0.f;
#pragma unroll
        for (int k = 0; k < 25; ++k) {
            float v = codebook[j * 25 + k];
            cb[j * 28 + k] = v;
            nrm = fmaf(v, v, nrm);
        }
        cb[j * 28 + 25] = 0.5f * nrm;
        cb[j * 28 + 26] = 0.f;
        cb[j * 28 + 27] = 0.f;
    }
    __syncthreads();

    const int pairId = (blockIdx.x * 1024 + tid) >> 1;   // [0, 65536)
    const int half = tid & 1;
    const int t0 = pairId;              // token 0
    const int t1 = pairId + 65536;      // token 1
    ull f0[13], f1[13];
    {
        const float* fv = g_vq + t0 * 25;
#pragma unroll
        for (int i = 0; i < 12; ++i) f0[i] = f2pk(fv[2 * i], fv[2 * i + 1]);
        f0[12] = f2pk(fv[24], -1.0f);
        const float* gv = g_vq + t1 * 25;
#pragma unroll
        for (int i = 0; i < 12; ++i) f1[i] = f2pk(gv[2 * i], gv[2 * i + 1]);
        f1[12] = f2pk(gv[24], -1.0f);
    }

    const float* cbh = cb + half * 512 * 28;
    const int jbase = half * 512;
    float best0 = -3.402823e38f, best1 = -3.402823e38f;
    int bi0 = 0, bi1 = 0;
    for (int j = 0; j < 512; ++j) {
        const ulonglong2* row = reinterpret_cast<const ulonglong2*>(cbh + j * 28);
        ulonglong2 v0 = row[0], v1 = row[1], v2 = row[2];
        ulonglong2 v3 = row[3], v4 = row[4], v5 = row[5];
        ull v6 = *(const ull*)(cbh + j * 28 + 24);   // (c24, 0.5||c||^2)
        ull a0 = f2mul(f0[0], v0.x);
        ull c0 = f2mul(f0[1], v0.y);
        ull a1 = f2mul(f1[0], v0.x);
        ull c1 = f2mul(f1[1], v0.y);
        a0 = f2fma(f0[2], v1.x, a0);  c0 = f2fma(f0[3], v1.y, c0);
        a1 = f2fma(f1[2], v1.x, a1);  c1 = f2fma(f1[3], v1.y, c1);
        a0 = f2fma(f0[4], v2.x, a0);  c0 = f2fma(f0[5], v2.y, c0);
        a1 = f2fma(f1[4], v2.x, a1);  c1 = f2fma(f1[5], v2.y, c1);
        a0 = f2fma(f0[6], v3.x, a0);  c0 = f2fma(f0[7], v3.y, c0);
        a1 = f2fma(f1[6], v3.x, a1);  c1 = f2fma(f1[7], v3.y, c1);
        a0 = f2fma(f0[8], v4.x, a0);  c0 = f2fma(f0[9], v4.y, c0);
        a1 = f2fma(f1[8], v4.x, a1);  c1 = f2fma(f1[9], v4.y, c1);
        a0 = f2fma(f0[10], v5.x, a0); c0 = f2fma(f0[11], v5.y, c0);
        a1 = f2fma(f1[10], v5.x, a1); c1 = f2fma(f1[11], v5.y, c1);
        a0 = f2fma(f0[12], v6, a0);
        a1 = f2fma(f1[12], v6, a1);
        float sc0 = f2sum(f2add(a0, c0));
        float sc1 = f2sum(f2add(a1, c1));
        if (sc0 > best0) { best0 = sc0; bi0 = jbase + j; }  // strict > == first
        if (sc1 > best1) { best1 = sc1; bi1 = jbase + j; }
    }

    // merge lane pairs: lo half has smaller indices, hi wins only if strictly >
    const float pb0 = __shfl_xor_sync(0xffffffffu, best0, 1);
    const int   pi0 = __shfl_xor_sync(0xffffffffu, bi0, 1);
    const float pb1 = __shfl_xor_sync(0xffffffffu, best1, 1);
    const int   pi1 = __shfl_xor_sync(0xffffffffu, bi1, 1);

    float ls = 0.f;
    if (half == 0) {
        const int m0 = (pb0 > best0) ? pi0 : bi0;
        const int m1 = (pb1 > best1) ? pi1 : bi1;
        g_ind[t0] = m0;
        g_ind[t1] = m1;
        // exact commitment-loss contributions (rows from global; same values)
        {
            const float* rr = codebook + m0 * 25;
#pragma unroll
            for (int i = 0; i < 12; ++i) {
                float lo, hi; f2un(f0[i], lo, hi);
                float d0 = rr[2 * i] - lo;     ls = fmaf(d0, d0, ls);
                float d1 = rr[2 * i + 1] - hi; ls = fmaf(d1, d1, ls);
            }
            float lo, hi; f2un(f0[12], lo, hi);
            float d = rr[24] - lo; ls = fmaf(d, d, ls);
        }
        {
            const float* rr = codebook + m1 * 25;
#pragma unroll
            for (int i = 0; i < 12; ++i) {
                float lo, hi; f2un(f1[i], lo, hi);
                float d0 = rr[2 * i] - lo;     ls = fmaf(d0, d0, ls);
                float d1 = rr[2 * i + 1] - hi; ls = fmaf(d1, d1, ls);
            }
            float lo, hi; f2un(f1[12], lo, hi);
            float d = rr[24] - lo; ls = fmaf(d, d, ls);
        }
    }
#pragma unroll
    for (int off = 16; off; off >>= 1) ls += __shfl_down_sync(0xffffffffu, ls, off);
    if ((tid & 31) == 0) sred[tid >> 5] = ls;
    __syncthreads();
    if (tid == 0) {
        float s = 0.f;
#pragma unroll
        for (int w = 0; w < 32; ++w) s += sred[w];
        g_lp[blockIdx.x] = s;
    }
}

__global__ void __launch_bounds__(128) kD2(float* __restrict__ out) {
    __shared__ float sred[4];
    const int tid = threadIdx.x;
    float s = g_lp[tid];
#pragma unroll
    for (int off = 16; off; off >>= 1) s += __shfl_down_sync(0xffffffffu, s, off);
    if ((tid & 31) == 0) sred[tid >> 5] = s;
    __syncthreads();
    if (tid == 0) {
        float t = 0.f;
#pragma unroll
        for (int w = 0; w < 4; ++w) t += sred[w];
        out[0] = t * (0.25f / 3276800.0f);
    }
}

// ---------------------------------------------------------------------------
// kE: gather codes, trans 1x1 (f32x2 s-pairs), pose head.  (R11 verbatim)
// ---------------------------------------------------------------------------
#define SMEM_E_FLOATS (3328 + 12288 + 2400)
#define KP_OFF (1 + 1228800)
__global__ void __launch_bounds__(512) kE(const float* __restrict__ codebook,
                                          const float* __restrict__ tw,
                                          const float* __restrict__ tb,
                                          const float* __restrict__ w1,
                                          const float* __restrict__ b1,
                                          const float* __restrict__ w2,
                                          const float* __restrict__ b2,
                                          float* __restrict__ out) {
    extern __shared__ float sm[];
    float* zr  = sm;            // 128 x 26 (col 25 = 0 pad)
    float* tws = zr + 3328;     // 12288
    float* lat = tws + 12288;   // 96 x 25
    __shared__ float part[512];
    __shared__ float hid[32];
    const int bb = blockIdx.x;
    const int tid = threadIdx.x;

    {
        const float4* s4 = (const float4*)tw;
        float4* d4 = (float4*)tws;
        for (int i = tid; i < 3072; i += 512) d4[i] = s4[i];
    }
    for (int el = tid; el < 3328; el += 512) {
        int i = el / 26, k = el % 26;
        float v = 0.f;
        if (k < 25) {
            int ci = g_ind[bb * 128 + i];
            v = codebook[ci * 25 + k];
        }
        zr[el] = v;
    }
    __syncthreads();

    for (int item = tid; item < 1248; item += 512) {
        const int oc = item / 13;
        const int s = (item % 13) * 2;
        ull acc = f2pk(0.f, 0.f);
#pragma unroll 4
        for (int i = 0; i < 128; ++i) {
            ull w = f2dup(tws[i * 96 + oc]);
            ull z = *(const ull*)(zr + i * 26 + s);
            acc = f2fma(w, z, acc);
        }
        float lo, hi; f2un(acc, lo, hi);
        const float bo = tb[oc];
        const float v0 = lo + bo;
        lat[oc * 25 + s] = v0;
        g_lat[bb * 2400 + oc * 25 + s] = v0;
        if (s + 1 < 25) {
            const float v1 = hi + bo;
            lat[oc * 25 + s + 1] = v1;
            g_lat[bb * 2400 + oc * 25 + s + 1] = v1;
        }
    }
    __syncthreads();

    const int warp = tid >> 5, lane = tid & 31;
    float a = 0.f;
    const int fbeg = warp * 150, fend = fbeg + 150;
    for (int f = fbeg; f < fend; ++f) a = fmaf(lat[f], w1[f * 32 + lane], a);
    part[warp * 32 + lane] = a;
    __syncthreads();
    if (tid < 32) {
        float s = b1[tid];
#pragma unroll
        for (int w = 0; w < 16; ++w) s += part[w * 32 + tid];
        hid[tid] = fmaxf(s, 0.f);
    }
    __syncthreads();
    if (tid < 36) {
        float acc = b2[tid];
#pragma unroll
        for (int h = 0; h < 32; ++h) acc = fmaf(hid[h], w2[h * 36 + tid], acc);
        out[KP_OFF + bb * 36 + tid] = acc;
    }
}

// ---------------------------------------------------------------------------
// kF: unpool2 + dec1 (row-based, ic-split partials) + relu + unpool1 + dec2.
// grid=1024, block=480.  (R11 verbatim)
// ---------------------------------------------------------------------------
#define SMEM_F_FLOATS (13824 + 27648 + 12800 + 864)
__global__ void __launch_bounds__(480) kF(const float* __restrict__ db1,
                                          const float* __restrict__ dw2,
                                          const float* __restrict__ db2,
                                          float* __restrict__ out) {
    extern __shared__ float sm[];
    float* u2p = sm;               // 96 x 12 x 12
    float* w1t = u2p + 13824;      // 27648
    float* uni = w1t + 27648;      // 12800: partials then u1
    float* w2s = uni + 12800;      // 864
    ull*   part = (ull*)uni;       // 4800 ull used
    __shared__ float b1s[32];
    __shared__ float b2s[3];
    const int bb = blockIdx.x;
    const int tid = threadIdx.x;

    for (int i = tid; i < 13824; i += 480) u2p[i] = 0.f;
    if (tid < 32) b1s[tid] = db1[tid];
    if (tid < 3) b2s[tid] = db2[tid];
    {
        const float4* s4 = (const float4*)g_w1t;
        float4* d4 = (float4*)w1t;
        for (int i = tid; i < 6912; i += 480) d4[i] = s4[i];
    }
    {
        const float4* s4 = (const float4*)dw2;
        float4* d4 = (float4*)w2s;
        for (int i = tid; i < 216; i += 480) d4[i] = s4[i];
    }
    __syncthreads();

    for (int el = tid; el < 2400; el += 480) {
        int c = el / 25, s = el % 25, py = s / 5, px = s % 5;
        float v = g_lat[bb * 2400 + el];
        int ii = g_i2[bb * 2400 + el];
        u2p[c * 144 + (2 * py + (ii >> 1) + 1) * 12 + (2 * px + (ii & 1) + 1)] = v;
    }
    __syncthreads();

    {
        const int wrp = tid / 32;        // 0..14
        const int icg = wrp / 5;         // 0..2
        const int prow = wrp % 5;        // 0..4
        const int oc = tid % 32;
        const float* tile = u2p + (2 * prow) * 12;
        ull acc0[5], acc1[5];
#pragma unroll
        for (int k = 0; k < 5; ++k) { acc0[k] = 0ull; acc1[k] = 0ull; }
        const int ic0 = icg * 32;
        for (int ic = ic0; ic < ic0 + 32; ++ic) {
            const float* wq = w1t + ic * 9 * 32 + oc;
            ull w0 = f2dup(wq[0]),   w1 = f2dup(wq[32]),  w2 = f2dup(wq[64]);
            ull w3 = f2dup(wq[96]),  w4 = f2dup(wq[128]), w5 = f2dup(wq[160]);
            ull w6 = f2dup(wq[192]), w7 = f2dup(wq[224]), w8 = f2dup(wq[256]);
            const float* cp = tile + ic * 144;
            Row R;
            load_row(cp, R);
            apply_row(R, w0, w1, w2, acc0);
            load_row(cp + 12, R);
            apply_row(R, w3, w4, w5, acc0);
            apply_row(R, w0, w1, w2, acc1);
            load_row(cp + 24, R);
            apply_row(R, w6, w7, w8, acc0);
            apply_row(R, w3, w4, w5, acc1);
            load_row(cp + 36, R);
            apply_row(R, w6, w7, w8, acc1);
        }
#pragma unroll
        for (int k = 0; k < 5; ++k) {
            part[(2 * k + 0) * 480 + tid] = acc0[k];
            part[(2 * k + 1) * 480 + tid] = acc1[k];
        }
    }
    __syncthreads();

    ull vv[10];
    if (tid < 160) {
        const int oc = tid % 32;
        const ull bco = f2dup(b1s[oc]);
#pragma unroll
        for (int q = 0; q < 10; ++q) {
            ull p0 = part[q * 480 + 0 * 160 + tid];
            ull p1 = part[q * 480 + 1 * 160 + tid];
            ull p2 = part[q * 480 + 2 * 160 + tid];
            vv[q] = f2add(f2add(f2add(bco, p0), p1), p2);
        }
    }
    __syncthreads();
    for (int i = tid; i < 12800; i += 480) uni[i] = 0.f;   // uni becomes u1
    __syncthreads();
    if (tid < 160) {
        const int prow = tid / 32;
        const int oc = tid % 32;
#pragma unroll
        for (int k = 0; k < 5; ++k)
#pragma unroll
            for (int dy = 0; dy < 2; ++dy) {
                float lo, hi; f2un(vv[2 * k + dy], lo, hi);
                const int y = 2 * prow + dy;
#pragma unroll
                for (int dx = 0; dx < 2; ++dx) {
                    const int x = 2 * k + dx;
                    float v = fmaxf(dx == 0 ? lo : hi, 0.f);
                    int ii = g_i1[bb * 3200 + oc * 100 + y * 10 + x];
                    uni[oc * 400 + (2 * y + (ii >> 1)) * 20 + (2 * x + (ii & 1))] = v;
                }
            }
    }
    __syncthreads();

    for (int o = tid; o < 1200; o += 480) {
        const int oc = o / 400;
        const int r = o % 400;
        const int y = r / 20, x = r % 20;
        float acc = b2s[oc];
        for (int ic = 0; ic < 32; ++ic) {
            const float* wp = w2s + (oc * 32 + ic) * 9;
            const float* up = uni + ic * 400;
#pragma unroll
            for (int kh = 0; kh < 3; ++kh) {
                const int yy = y + kh - 1;
                if ((unsigned)yy < 20u) {
#pragma unroll
                    for (int kw = 0; kw < 3; ++kw) {
                        const int xx = x + kw - 1;
                        if ((unsigned)xx < 20u)
                            acc = fmaf(wp[kh * 3 + kw], up[yy * 20 + xx], acc);
                    }
                }
            }
        }
        out[1 + bb * 1200 + o] = acc;
    }
}

// ---------------------------------------------------------------------------
extern "C" void kernel_launch(void* const* d_in, const int* in_sizes, int n_in,
                              void* d_out, int out_size) {
    const float* x    = (const float*)d_in[0];
    const float* e1w  = (const float*)d_in[1];
    const float* e1b  = (const float*)d_in[2];
    const float* e2w  = (const float*)d_in[3];
    const float* e2b  = (const float*)d_in[4];
    const float* prew = (const float*)d_in[5];
    const float* preb = (const float*)d_in[6];
    const float* cbk  = (const float*)d_in[7];
    const float* trw  = (const float*)d_in[8];
    const float* trb  = (const float*)d_in[9];
    const float* d1w  = (const float*)d_in[10];
    const float* d1b  = (const float*)d_in[11];
    const float* d2w  = (const float*)d_in[12];
    const float* d2b  = (const float*)d_in[13];
    const float* hw1  = (const float*)d_in[14];
    const float* hb1  = (const float*)d_in[15];
    const float* hw2  = (const float*)d_in[16];
    const float* hb2  = (const float*)d_in[17];
    float* out = (float*)d_out;

    cudaFuncSetAttribute(kB, cudaFuncAttributeMaxDynamicSharedMemorySize, SMEM_B_FLOATS * 4);
    cudaFuncSetAttribute(kD, cudaFuncAttributeMaxDynamicSharedMemorySize, SMEM_D_FLOATS * 4);
    cudaFuncSetAttribute(kE, cudaFuncAttributeMaxDynamicSharedMemorySize, SMEM_E_FLOATS * 4);
    cudaFuncSetAttribute(kF, cudaFuncAttributeMaxDynamicSharedMemorySize, SMEM_F_FLOATS * 4);

    kT<<<108, 512>>>(e2w, d1w);
    kA<<<NB, 320>>>(x, e1w, e1b);
    kB<<<512, 480, SMEM_B_FLOATS * 4>>>(e2b, prew, preb);
    kD<<<128, 1024, SMEM_D_FLOATS * 4>>>(cbk);
    kD2<<<1, 128>>>(out);
    kE<<<NB, 512, SMEM_E_FLOATS * 4>>>(cbk, trw, trb, hw1, hb1, hw2, hb2, out);
    kF<<<NB, 480, SMEM_F_FLOATS * 4>>>(d1b, d2w, d2b, out);
}

// round 13
// speedup vs baseline: 1.1824x; 1.1824x over previous
#include <cuda_runtime.h>
#include <cstdint>

// ---------------------------------------------------------------------------
// EfficientFi VQ-VAE forward, B=1024.  Round 13: best-known composition —
// R11's kA/kB/kE/kF + R10's kD verbatim (2-token, block 512, no unroll).
// ---------------------------------------------------------------------------

#define NB 1024
typedef unsigned long long ull;

__device__ float         g_p1[NB * 3200];
__device__ unsigned char g_i1[NB * 3200];
__device__ float         g_vq[NB * 3200];
__device__ unsigned char g_i2[NB * 2400];
__device__ int           g_ind[NB * 128];
__device__ float         g_lat[NB * 2400];
__device__ float         g_lp[128];
__device__ float         g_w2t[27648];   // enc2 weights transposed [(ic*9+k)][96]
__device__ float         g_w1t[27648];   // dec1 weights transposed [(ic*9+k)][32]

// ---------------- f32x2 packed helpers (sm_103a) ----------------
static __device__ __forceinline__ ull f2pk(float a, float b) {
    ull r; asm("mov.b64 %0, {%1, %2};" : "=l"(r) : "f"(a), "f"(b)); return r;
}
static __device__ __forceinline__ void f2un(ull v, float& lo, float& hi) {
    asm("mov.b64 {%0, %1}, %2;" : "=f"(lo), "=f"(hi) : "l"(v));
}
static __device__ __forceinline__ ull f2dup(float a) { return f2pk(a, a); }
static __device__ __forceinline__ ull f2mul(ull a, ull b) {
    ull d; asm("mul.rn.f32x2 %0, %1, %2;" : "=l"(d) : "l"(a), "l"(b)); return d;
}
static __device__ __forceinline__ ull f2fma(ull a, ull b, ull c) {
    ull d; asm("fma.rn.f32x2 %0, %1, %2, %3;" : "=l"(d) : "l"(a), "l"(b), "l"(c)); return d;
}
static __device__ __forceinline__ ull f2add(ull a, ull b) {
    ull d; asm("add.rn.f32x2 %0, %1, %2;" : "=l"(d) : "l"(a), "l"(b)); return d;
}
static __device__ __forceinline__ float f2sum(ull v) {
    float lo, hi; f2un(v, lo, hi); return lo + hi;
}
static __device__ __forceinline__ ull f2mid(ull a, ull b) {
    float alo, ahi, blo, bhi; f2un(a, alo, ahi); f2un(b, blo, bhi);
    return f2pk(ahi, blo);
}

// 12-wide padded row: 6 pairs + 5 mids (kB/kF tiles)
struct Row { ull P[6]; ull M[5]; };
static __device__ __forceinline__ void load_row(const float* __restrict__ rp, Row& R) {
    ulonglong2 q0 = *(const ulonglong2*)(rp);
    ulonglong2 q1 = *(const ulonglong2*)(rp + 4);
    ulonglong2 q2 = *(const ulonglong2*)(rp + 8);
    R.P[0] = q0.x; R.P[1] = q0.y; R.P[2] = q1.x; R.P[3] = q1.y; R.P[4] = q2.x; R.P[5] = q2.y;
#pragma unroll
    for (int k = 0; k < 5; ++k) R.M[k] = f2mid(R.P[k], R.P[k + 1]);
}
static __device__ __forceinline__ void apply_row(const Row& R, ull wa, ull wb, ull wc, ull* acc) {
#pragma unroll
    for (int k = 0; k < 5; ++k) {
        acc[k] = f2fma(wa, R.P[k], acc[k]);
        acc[k] = f2fma(wb, R.M[k], acc[k]);
        acc[k] = f2fma(wc, R.P[k + 1], acc[k]);
    }
}

// 24-wide padded row: 11 pairs + 10 mids (kA tile)
struct Row24 { ull P[11]; ull M[10]; };
static __device__ __forceinline__ void load_row24(const float* __restrict__ rp, Row24& R) {
    ulonglong2 q0 = *(const ulonglong2*)(rp);
    ulonglong2 q1 = *(const ulonglong2*)(rp + 4);
    ulonglong2 q2 = *(const ulonglong2*)(rp + 8);
    ulonglong2 q3 = *(const ulonglong2*)(rp + 12);
    ulonglong2 q4 = *(const ulonglong2*)(rp + 16);
    R.P[0] = q0.x; R.P[1] = q0.y; R.P[2] = q1.x; R.P[3] = q1.y; R.P[4] = q2.x;
    R.P[5] = q2.y; R.P[6] = q3.x; R.P[7] = q3.y; R.P[8] = q4.x; R.P[9] = q4.y;
    R.P[10] = *(const ull*)(rp + 20);
#pragma unroll
    for (int k = 0; k < 10; ++k) R.M[k] = f2mid(R.P[k], R.P[k + 1]);
}
static __device__ __forceinline__ void apply_row24(const Row24& R, ull wa, ull wb, ull wc, ull* acc) {
#pragma unroll
    for (int k = 0; k < 10; ++k) {
        acc[k] = f2fma(wa, R.P[k], acc[k]);
        acc[k] = f2fma(wb, R.M[k], acc[k]);
        acc[k] = f2fma(wc, R.P[k + 1], acc[k]);
    }
}

static __device__ __forceinline__ void pool_epi(ull r0, ull r1, float& best, int& bi) {
    float a00, a01, a10, a11;
    f2un(r0, a00, a01); f2un(r1, a10, a11);
    float v00 = fmaxf(a00, 0.f), v01 = fmaxf(a01, 0.f);
    float v10 = fmaxf(a10, 0.f), v11 = fmaxf(a11, 0.f);
    best = v00; bi = 0;
    if (v01 > best) { best = v01; bi = 1; }
    if (v10 > best) { best = v10; bi = 2; }
    if (v11 > best) { best = v11; bi = 3; }
}

// ---------------------------------------------------------------------------
// kT: one-shot weight transposer.  grid=108, block=512.
// ---------------------------------------------------------------------------
__global__ void __launch_bounds__(512) kT(const float* __restrict__ e2w,
                                          const float* __restrict__ d1w) {
    int i = blockIdx.x * 512 + threadIdx.x;
    if (i < 27648) {
        int kidx = i / 96, oc = i % 96;
        g_w2t[i] = e2w[oc * 288 + kidx];
    } else if (i < 55296) {
        int j = i - 27648;
        int kidx = j / 32, oc = j % 32;
        g_w1t[j] = d1w[oc * 864 + kidx];
    }
}

// ---------------------------------------------------------------------------
// kA: conv1 + relu + pool1, row-based f32x2.  grid=1024, block=320.
// ---------------------------------------------------------------------------
__global__ void __launch_bounds__(320) kA(const float* __restrict__ x,
                                          const float* __restrict__ w,
                                          const float* __restrict__ bias) {
    __shared__ float xp[1728];  // 3 x 24 x 24
    __shared__ float ws[864];
    __shared__ float bs[32];
    const int bb = blockIdx.x;
    const int tid = threadIdx.x;

    for (int i = tid; i < 1728; i += 320) xp[i] = 0.f;
    __syncthreads();
    for (int i = tid; i < 1200; i += 320) {
        int c = i / 400, r = i % 400, y = r / 20, xx = r % 20;
        xp[c * 576 + (y + 1) * 24 + (xx + 1)] = x[bb * 1200 + i];
    }
    for (int i = tid; i < 864; i += 320) ws[i] = w[i];
    if (tid < 32) bs[tid] = bias[tid];
    __syncthreads();

    const int oc = tid & 31;
    const int prow = tid >> 5;         // 0..9
    ull acc0[10], acc1[10];
    {
        ull b = f2dup(bs[oc]);
#pragma unroll
        for (int k = 0; k < 10; ++k) { acc0[k] = b; acc1[k] = b; }
    }
#pragma unroll
    for (int c = 0; c < 3; ++c) {
        const float* wp = ws + (oc * 3 + c) * 9;
        ull w0 = f2dup(wp[0]), w1 = f2dup(wp[1]), w2 = f2dup(wp[2]);
        ull w3 = f2dup(wp[3]), w4 = f2dup(wp[4]), w5 = f2dup(wp[5]);
        ull w6 = f2dup(wp[6]), w7 = f2dup(wp[7]), w8 = f2dup(wp[8]);
        const float* cp = xp + c * 576 + (2 * prow) * 24;
        Row24 R;
        load_row24(cp, R);
        apply_row24(R, w0, w1, w2, acc0);
        load_row24(cp + 24, R);
        apply_row24(R, w3, w4, w5, acc0);
        apply_row24(R, w0, w1, w2, acc1);
        load_row24(cp + 48, R);
        apply_row24(R, w6, w7, w8, acc0);
        apply_row24(R, w3, w4, w5, acc1);
        load_row24(cp + 72, R);
        apply_row24(R, w6, w7, w8, acc1);
    }
#pragma unroll
    for (int k = 0; k < 10; ++k) {
        float best; int bi;
        pool_epi(acc0[k], acc1[k], best, bi);
        const int cell = oc * 100 + prow * 10 + k;
        g_p1[bb * 3200 + cell] = best;
        g_i1[bb * 3200 + cell] = (unsigned char)bi;
    }
}

// ---------------------------------------------------------------------------
// kB: conv2+relu+pool2 (row-based) + pre 1x1 (img-pair, float4 w).
// grid=512 (2 images/CTA), block=480.
// ---------------------------------------------------------------------------
#define SMEM_B_FLOATS (2 * 4608 + 27648 + 96 + 2 * 2400 + 12288 + 128)
__global__ void __launch_bounds__(480) kB(const float* __restrict__ b2,
                                          const float* __restrict__ pw,
                                          const float* __restrict__ pb) {
    extern __shared__ float sm[];
    float* p1p = sm;              // 2 x (32 x 12 x 12)
    float* w2t = p1p + 9216;      // 27648
    float* b2s = w2t + 27648;     // 96
    float* zs  = b2s + 96;        // 2 x (96 x 25)
    float* pws = zs + 4800;       // 12288
    float* pbs = pws + 12288;     // 128
    const int bb = blockIdx.x;
    const int tid = threadIdx.x;

    for (int i = tid; i < 9216; i += 480) p1p[i] = 0.f;
    __syncthreads();
    for (int i = tid; i < 6400; i += 480) {
        int img = i / 3200, r0 = i % 3200;
        int c = r0 / 100, r = r0 % 100, y = r / 10, xx = r % 10;
        p1p[img * 4608 + c * 144 + (y + 1) * 12 + (xx + 1)] = g_p1[(2 * bb + img) * 3200 + r0];
    }
    {
        const float4* s4 = (const float4*)g_w2t;
        float4* d4 = (float4*)w2t;
        for (int i = tid; i < 6912; i += 480) d4[i] = s4[i];
    }
    if (tid < 96) b2s[tid] = b2[tid];
    {
        const float4* s4 = (const float4*)pw;
        float4* d4 = (float4*)pws;
        for (int i = tid; i < 3072; i += 480) d4[i] = s4[i];
    }
    if (tid < 128) pbs[tid] = pb[tid];
    __syncthreads();

    const int item_oc = tid % 96;
    const int prow = tid / 96;            // 0..4
#pragma unroll
    for (int img = 0; img < 2; ++img) {
        const float* tile = p1p + img * 4608 + (2 * prow) * 12;
        float* zsi = zs + img * 2400;
        ull acc0[5], acc1[5];
        {
            ull b = f2dup(b2s[item_oc]);
#pragma unroll
            for (int k = 0; k < 5; ++k) { acc0[k] = b; acc1[k] = b; }
        }
        for (int ic = 0; ic < 32; ++ic) {
            const float* wq = w2t + ic * 9 * 96 + item_oc;
            ull w0 = f2dup(wq[0]),     w1 = f2dup(wq[96]),    w2 = f2dup(wq[192]);
            ull w3 = f2dup(wq[288]),   w4 = f2dup(wq[384]),   w5 = f2dup(wq[480]);
            ull w6 = f2dup(wq[576]),   w7 = f2dup(wq[672]),   w8 = f2dup(wq[768]);
            const float* cp = tile + ic * 144;
            Row R;
            load_row(cp, R);
            apply_row(R, w0, w1, w2, acc0);
            load_row(cp + 12, R);
            apply_row(R, w3, w4, w5, acc0);
            apply_row(R, w0, w1, w2, acc1);
            load_row(cp + 24, R);
            apply_row(R, w6, w7, w8, acc0);
            apply_row(R, w3, w4, w5, acc1);
            load_row(cp + 36, R);
            apply_row(R, w6, w7, w8, acc1);
        }
#pragma unroll
        for (int k = 0; k < 5; ++k) {
            float best; int bi;
            pool_epi(acc0[k], acc1[k], best, bi);
            const int cell = item_oc * 25 + prow * 5 + k;
            zsi[cell] = best;
            g_i2[(2 * bb + img) * 2400 + cell] = (unsigned char)bi;
        }
    }
    __syncthreads();

    // pre 1x1 — per-output chain byte-identical to R6; weights float4, img-pair.
    for (int o = tid; o < 3200; o += 480) {
        const int e = o / 25, s = o % 25;
        const float* wp = pws + e * 96;
        const float* z0 = zs;
        const float* z1 = zs + 2400;
        float a0 = 0.f, a1 = 0.f, a2 = 0.f, a3 = 0.f;
        float b0 = 0.f, b1 = 0.f, b2v = 0.f, b3 = 0.f;
#pragma unroll 4
        for (int c = 0; c < 96; c += 4) {
            const float4 wv = *(const float4*)(wp + c);
            a0 = fmaf(wv.x, z0[(c + 0) * 25 + s], a0);
            a1 = fmaf(wv.y, z0[(c + 1) * 25 + s], a1);
            a2 = fmaf(wv.z, z0[(c + 2) * 25 + s], a2);
            a3 = fmaf(wv.w, z0[(c + 3) * 25 + s], a3);
            b0 = fmaf(wv.x, z1[(c + 0) * 25 + s], b0);
            b1 = fmaf(wv.y, z1[(c + 1) * 25 + s], b1);
            b2v = fmaf(wv.z, z1[(c + 2) * 25 + s], b2v);
            b3 = fmaf(wv.w, z1[(c + 3) * 25 + s], b3);
        }
        g_vq[(2 * bb + 0) * 3200 + o] = (a0 + a1) + (a2 + a3) + pbs[e];
        g_vq[(2 * bb + 1) * 3200 + o] = (b0 + b1) + (b2v + b3) + pbs[e];
    }
}

// ---------------------------------------------------------------------------
// kD: VQ argmin, 2 tokens/thread. grid=128, block=512. smem 114688 B.
// R10 verbatim (190 us measured; chain identical to R5-passing version).
// ---------------------------------------------------------------------------
#define SMEM_D_FLOATS (1024 * 28)
__global__ void __launch_bounds__(512) kD(const float* __restrict__ codebook) {
    extern __shared__ float cb[];
    __shared__ float sred[16];
    const int tid = threadIdx.x;

    for (int j = tid; j < 1024; j += 512) {
        float nrm = 0.f;
#pragma unroll
        for (int k = 0; k < 25; ++k) {
            float v = codebook[j * 25 + k];
            cb[j * 28 + k] = v;
            nrm = fmaf(v, v, nrm);
        }
        cb[j * 28 + 25] = 0.5f * nrm;
        cb[j * 28 + 26] = 0.f;
        cb[j * 28 + 27] = 0.f;
    }
    __syncthreads();

    const int t0 = blockIdx.x * 1024 + tid;   // sibling token: t0 + 512
    ull f0[13], f1[13];
    {
        const float* fv = g_vq + t0 * 25;
#pragma unroll
        for (int i = 0; i < 12; ++i) f0[i] = f2pk(fv[2 * i], fv[2 * i + 1]);
        f0[12] = f2pk(fv[24], -1.0f);
        const float* gv = g_vq + (t0 + 512) * 25;
#pragma unroll
        for (int i = 0; i < 12; ++i) f1[i] = f2pk(gv[2 * i], gv[2 * i + 1]);
        f1[12] = f2pk(gv[24], -1.0f);
    }

    float best0 = -3.402823e38f, best1 = -3.402823e38f;
    int bi0 = 0, bi1 = 0;
    for (int j = 0; j < 1024; ++j) {
        const ulonglong2* row = reinterpret_cast<const ulonglong2*>(cb + j * 28);
        ulonglong2 v0 = row[0], v1 = row[1], v2 = row[2];
        ulonglong2 v3 = row[3], v4 = row[4], v5 = row[5];
        ull v6 = *(const ull*)(cb + j * 28 + 24);   // (c24, 0.5||c||^2)
        ull a0 = f2mul(f0[0], v0.x);
        ull c0 = f2mul(f0[1], v0.y);
        ull a1 = f2mul(f1[0], v0.x);
        ull c1 = f2mul(f1[1], v0.y);
        a0 = f2fma(f0[2], v1.x, a0);  c0 = f2fma(f0[3], v1.y, c0);
        a1 = f2fma(f1[2], v1.x, a1);  c1 = f2fma(f1[3], v1.y, c1);
        a0 = f2fma(f0[4], v2.x, a0);  c0 = f2fma(f0[5], v2.y, c0);
        a1 = f2fma(f1[4], v2.x, a1);  c1 = f2fma(f1[5], v2.y, c1);
        a0 = f2fma(f0[6], v3.x, a0);  c0 = f2fma(f0[7], v3.y, c0);
        a1 = f2fma(f1[6], v3.x, a1);  c1 = f2fma(f1[7], v3.y, c1);
        a0 = f2fma(f0[8], v4.x, a0);  c0 = f2fma(f0[9], v4.y, c0);
        a1 = f2fma(f1[8], v4.x, a1);  c1 = f2fma(f1[9], v4.y, c1);
        a0 = f2fma(f0[10], v5.x, a0); c0 = f2fma(f0[11], v5.y, c0);
        a1 = f2fma(f1[10], v5.x, a1); c1 = f2fma(f1[11], v5.y, c1);
        a0 = f2fma(f0[12], v6, a0);
        a1 = f2fma(f1[12], v6, a1);
        float sc0 = f2sum(f2add(a0, c0));
        float sc1 = f2sum(f2add(a1, c1));
        if (sc0 > best0) { best0 = sc0; bi0 = j; }   // strict > == first-argmin
        if (sc1 > best1) { best1 = sc1; bi1 = j; }
    }
    g_ind[t0] = bi0;
    g_ind[t0 + 512] = bi1;

    // exact commitment-loss contributions
    float ls = 0.f;
    {
        const float* rr = cb + bi0 * 28;
#pragma unroll
        for (int i = 0; i < 12; ++i) {
            float lo, hi; f2un(f0[i], lo, hi);
            float d0 = rr[2 * i] - lo;     ls = fmaf(d0, d0, ls);
            float d1 = rr[2 * i + 1] - hi; ls = fmaf(d1, d1, ls);
        }
        float lo, hi; f2un(f0[12], lo, hi);
        float d = rr[24] - lo; ls = fmaf(d, d, ls);
    }
    {
        const float* rr = cb + bi1 * 28;
#pragma unroll
        for (int i = 0; i < 12; ++i) {
            float lo, hi; f2un(f1[i], lo, hi);
            float d0 = rr[2 * i] - lo;     ls = fmaf(d0, d0, ls);
            float d1 = rr[2 * i + 1] - hi; ls = fmaf(d1, d1, ls);
        }
        float lo, hi; f2un(f1[12], lo, hi);
        float d = rr[24] - lo; ls = fmaf(d, d, ls);
    }
#pragma unroll
    for (int off = 16; off; off >>= 1) ls += __shfl_down_sync(0xffffffffu, ls, off);
    if ((tid & 31) == 0) sred[tid >> 5] = ls;
    __syncthreads();
    if (tid == 0) {
        float s = 0.f;
#pragma unroll
        for (int w = 0; w < 16; ++w) s += sred[w];
        g_lp[blockIdx.x] = s;
    }
}

__global__ void __launch_bounds__(128) kD2(float* __restrict__ out) {
    __shared__ float sred[4];
    const int tid = threadIdx.x;
    float s = g_lp[tid];
#pragma unroll
    for (int off = 16; off; off >>= 1) s += __shfl_down_sync(0xffffffffu, s, off);
    if ((tid & 31) == 0) sred[tid >> 5] = s;
    __syncthreads();
    if (tid == 0) {
        float t = 0.f;
#pragma unroll
        for (int w = 0; w < 4; ++w) t += sred[w];
        out[0] = t * (0.25f / 3276800.0f);
    }
}

// ---------------------------------------------------------------------------
// kE: gather codes, trans 1x1 (f32x2 s-pairs), pose head.  (R11 verbatim)
// ---------------------------------------------------------------------------
#define SMEM_E_FLOATS (3328 + 12288 + 2400)
#define KP_OFF (1 + 1228800)
__global__ void __launch_bounds__(512) kE(const float* __restrict__ codebook,
                                          const float* __restrict__ tw,
                                          const float* __restrict__ tb,
                                          const float* __restrict__ w1,
                                          const float* __restrict__ b1,
                                          const float* __restrict__ w2,
                                          const float* __restrict__ b2,
                                          float* __restrict__ out) {
    extern __shared__ float sm[];
    float* zr  = sm;            // 128 x 26 (col 25 = 0 pad)
    float* tws = zr + 3328;     // 12288
    float* lat = tws + 12288;   // 96 x 25
    __shared__ float part[512];
    __shared__ float hid[32];
    const int bb = blockIdx.x;
    const int tid = threadIdx.x;

    {
        const float4* s4 = (const float4*)tw;
        float4* d4 = (float4*)tws;
        for (int i = tid; i < 3072; i += 512) d4[i] = s4[i];
    }
    for (int el = tid; el < 3328; el += 512) {
        int i = el / 26, k = el % 26;
        float v = 0.f;
        if (k < 25) {
            int ci = g_ind[bb * 128 + i];
            v = codebook[ci * 25 + k];
        }
        zr[el] = v;
    }
    __syncthreads();

    for (int item = tid; item < 1248; item += 512) {
        const int oc = item / 13;
        const int s = (item % 13) * 2;
        ull acc = f2pk(0.f, 0.f);
#pragma unroll 4
        for (int i = 0; i < 128; ++i) {
            ull w = f2dup(tws[i * 96 + oc]);
            ull z = *(const ull*)(zr + i * 26 + s);
            acc = f2fma(w, z, acc);
        }
        float lo, hi; f2un(acc, lo, hi);
        const float bo = tb[oc];
        const float v0 = lo + bo;
        lat[oc * 25 + s] = v0;
        g_lat[bb * 2400 + oc * 25 + s] = v0;
        if (s + 1 < 25) {
            const float v1 = hi + bo;
            lat[oc * 25 + s + 1] = v1;
            g_lat[bb * 2400 + oc * 25 + s + 1] = v1;
        }
    }
    __syncthreads();

    const int warp = tid >> 5, lane = tid & 31;
    float a = 0.f;
    const int fbeg = warp * 150, fend = fbeg + 150;
    for (int f = fbeg; f < fend; ++f) a = fmaf(lat[f], w1[f * 32 + lane], a);
    part[warp * 32 + lane] = a;
    __syncthreads();
    if (tid < 32) {
        float s = b1[tid];
#pragma unroll
        for (int w = 0; w < 16; ++w) s += part[w * 32 + tid];
        hid[tid] = fmaxf(s, 0.f);
    }
    __syncthreads();
    if (tid < 36) {
        float acc = b2[tid];
#pragma unroll
        for (int h = 0; h < 32; ++h) acc = fmaf(hid[h], w2[h * 36 + tid], acc);
        out[KP_OFF + bb * 36 + tid] = acc;
    }
}

// ---------------------------------------------------------------------------
// kF: unpool2 + dec1 (row-based, ic-split partials) + relu + unpool1 + dec2.
// grid=1024, block=480.  (R11 verbatim)
// ---------------------------------------------------------------------------
#define SMEM_F_FLOATS (13824 + 27648 + 12800 + 864)
__global__ void __launch_bounds__(480) kF(const float* __restrict__ db1,
                                          const float* __restrict__ dw2,
                                          const float* __restrict__ db2,
                                          float* __restrict__ out) {
    extern __shared__ float sm[];
    float* u2p = sm;               // 96 x 12 x 12
    float* w1t = u2p + 13824;      // 27648
    float* uni = w1t + 27648;      // 12800: partials then u1
    float* w2s = uni + 12800;      // 864
    ull*   part = (ull*)uni;       // 4800 ull used
    __shared__ float b1s[32];
    __shared__ float b2s[3];
    const int bb = blockIdx.x;
    const int tid = threadIdx.x;

    for (int i = tid; i < 13824; i += 480) u2p[i] = 0.f;
    if (tid < 32) b1s[tid] = db1[tid];
    if (tid < 3) b2s[tid] = db2[tid];
    {
        const float4* s4 = (const float4*)g_w1t;
        float4* d4 = (float4*)w1t;
        for (int i = tid; i < 6912; i += 480) d4[i] = s4[i];
    }
    {
        const float4* s4 = (const float4*)dw2;
        float4* d4 = (float4*)w2s;
        for (int i = tid; i < 216; i += 480) d4[i] = s4[i];
    }
    __syncthreads();

    for (int el = tid; el < 2400; el += 480) {
        int c = el / 25, s = el % 25, py = s / 5, px = s % 5;
        float v = g_lat[bb * 2400 + el];
        int ii = g_i2[bb * 2400 + el];
        u2p[c * 144 + (2 * py + (ii >> 1) + 1) * 12 + (2 * px + (ii & 1) + 1)] = v;
    }
    __syncthreads();

    {
        const int wrp = tid / 32;        // 0..14
        const int icg = wrp / 5;         // 0..2
        const int prow = wrp % 5;        // 0..4
        const int oc = tid % 32;
        const float* tile = u2p + (2 * prow) * 12;
        ull acc0[5], acc1[5];
#pragma unroll
        for (int k = 0; k < 5; ++k) { acc0[k] = 0ull; acc1[k] = 0ull; }
        const int ic0 = icg * 32;
        for (int ic = ic0; ic < ic0 + 32; ++ic) {
            const float* wq = w1t + ic * 9 * 32 + oc;
            ull w0 = f2dup(wq[0]),   w1 = f2dup(wq[32]),  w2 = f2dup(wq[64]);
            ull w3 = f2dup(wq[96]),  w4 = f2dup(wq[128]), w5 = f2dup(wq[160]);
            ull w6 = f2dup(wq[192]), w7 = f2dup(wq[224]), w8 = f2dup(wq[256]);
            const float* cp = tile + ic * 144;
            Row R;
            load_row(cp, R);
            apply_row(R, w0, w1, w2, acc0);
            load_row(cp + 12, R);
            apply_row(R, w3, w4, w5, acc0);
            apply_row(R, w0, w1, w2, acc1);
            load_row(cp + 24, R);
            apply_row(R, w6, w7, w8, acc0);
            apply_row(R, w3, w4, w5, acc1);
            load_row(cp + 36, R);
            apply_row(R, w6, w7, w8, acc1);
        }
#pragma unroll
        for (int k = 0; k < 5; ++k) {
            part[(2 * k + 0) * 480 + tid] = acc0[k];
            part[(2 * k + 1) * 480 + tid] = acc1[k];
        }
    }
    __syncthreads();

    ull vv[10];
    if (tid < 160) {
        const int oc = tid % 32;
        const ull bco = f2dup(b1s[oc]);
#pragma unroll
        for (int q = 0; q < 10; ++q) {
            ull p0 = part[q * 480 + 0 * 160 + tid];
            ull p1 = part[q * 480 + 1 * 160 + tid];
            ull p2 = part[q * 480 + 2 * 160 + tid];
            vv[q] = f2add(f2add(f2add(bco, p0), p1), p2);
        }
    }
    __syncthreads();
    for (int i = tid; i < 12800; i += 480) uni[i] = 0.f;   // uni becomes u1
    __syncthreads();
    if (tid < 160) {
        const int prow = tid / 32;
        const int oc = tid % 32;
#pragma unroll
        for (int k = 0; k < 5; ++k)
#pragma unroll
            for (int dy = 0; dy < 2; ++dy) {
                float lo, hi; f2un(vv[2 * k + dy], lo, hi);
                const int y = 2 * prow + dy;
#pragma unroll
                for (int dx = 0; dx < 2; ++dx) {
                    const int x = 2 * k + dx;
                    float v = fmaxf(dx == 0 ? lo : hi, 0.f);
                    int ii = g_i1[bb * 3200 + oc * 100 + y * 10 + x];
                    uni[oc * 400 + (2 * y + (ii >> 1)) * 20 + (2 * x + (ii & 1))] = v;
                }
            }
    }
    __syncthreads();

    for (int o = tid; o < 1200; o += 480) {
        const int oc = o / 400;
        const int r = o % 400;
        const int y = r / 20, x = r % 20;
        float acc = b2s[oc];
        for (int ic = 0; ic < 32; ++ic) {
            const float* wp = w2s + (oc * 32 + ic) * 9;
            const float* up = uni + ic * 400;
#pragma unroll
            for (int kh = 0; kh < 3; ++kh) {
                const int yy = y + kh - 1;
                if ((unsigned)yy < 20u) {
#pragma unroll
                    for (int kw = 0; kw < 3; ++kw) {
                        const int xx = x + kw - 1;
                        if ((unsigned)xx < 20u)
                            acc = fmaf(wp[kh * 3 + kw], up[yy * 20 + xx], acc);
                    }
                }
            }
        }
        out[1 + bb * 1200 + o] = acc;
    }
}

// ---------------------------------------------------------------------------
extern "C" void kernel_launch(void* const* d_in, const int* in_sizes, int n_in,
                              void* d_out, int out_size) {
    const float* x    = (const float*)d_in[0];
    const float* e1w  = (const float*)d_in[1];
    const float* e1b  = (const float*)d_in[2];
    const float* e2w  = (const float*)d_in[3];
    const float* e2b  = (const float*)d_in[4];
    const float* prew = (const float*)d_in[5];
    const float* preb = (const float*)d_in[6];
    const float* cbk  = (const float*)d_in[7];
    const float* trw  = (const float*)d_in[8];
    const float* trb  = (const float*)d_in[9];
    const float* d1w  = (const float*)d_in[10];
    const float* d1b  = (const float*)d_in[11];
    const float* d2w  = (const float*)d_in[12];
    const float* d2b  = (const float*)d_in[13];
    const float* hw1  = (const float*)d_in[14];
    const float* hb1  = (const float*)d_in[15];
    const float* hw2  = (const float*)d_in[16];
    const float* hb2  = (const float*)d_in[17];
    float* out = (float*)d_out;

    cudaFuncSetAttribute(kB, cudaFuncAttributeMaxDynamicSharedMemorySize, SMEM_B_FLOATS * 4);
    cudaFuncSetAttribute(kD, cudaFuncAttributeMaxDynamicSharedMemorySize, SMEM_D_FLOATS * 4);
    cudaFuncSetAttribute(kE, cudaFuncAttributeMaxDynamicSharedMemorySize, SMEM_E_FLOATS * 4);
    cudaFuncSetAttribute(kF, cudaFuncAttributeMaxDynamicSharedMemorySize, SMEM_F_FLOATS * 4);

    kT<<<108, 512>>>(e2w, d1w);
    kA<<<NB, 320>>>(x, e1w, e1b);
    kB<<<512, 480, SMEM_B_FLOATS * 4>>>(e2b, prew, preb);
    kD<<<128, 512, SMEM_D_FLOATS * 4>>>(cbk);
    kD2<<<1, 128>>>(out);
    kE<<<NB, 512, SMEM_E_FLOATS * 4>>>(cbk, trw, trb, hw1, hb1, hw2, hb2, out);
    kF<<<NB, 480, SMEM_F_FLOATS * 4>>>(d1b, d2w, d2b, out);
}